// round 5
// baseline (speedup 1.0000x reference)
#include <cuda_runtime.h>
#include <cstdint>

#define B_   8
#define N_   64
#define NUM_CLASSES 81
#define C_   86
#define NLEV 5
#define TOTAL_G2 10912   // 2-pixel groups per batch: 8192+2048+512+128+32

__constant__ int   c_H[NLEV]     = {128, 64, 32, 16, 8};
__constant__ int   c_logH[NLEV]  = {7, 6, 5, 4, 3};
__constant__ float c_ps[NLEV]    = {0.0078125f, 0.015625f, 0.03125f, 0.0625f, 0.125f};
__constant__ float c_invps[NLEV] = {128.0f, 64.0f, 32.0f, 16.0f, 8.0f};
__constant__ float c_th0[NLEV]   = {0.0078125f, 0.0625f, 0.125f, 0.25f, 0.5f};
__constant__ float c_th1[NLEV]   = {0.0625f, 0.125f, 0.25f, 0.5f, 1.0f};
__constant__ size_t c_base[NLEV] = {0ull, 11272192ull, 14090240ull, 14794752ull, 14970880ull};
__constant__ int   c_gbase2[NLEV]= {0, 8192, 10240, 10752, 10880};

// scratch (no allocation allowed)
__device__ float4             g_sboxes[B_][N_];
__device__ int                g_slabels[B_][N_];
__device__ unsigned long long g_cov[B_][NLEV][128][2];  // fg_any bitmask per row
__device__ unsigned long long g_cand[B_][NLEV][128];    // candidate boxes per row

// ---------------- K1: sort + per-row masks ----------------
__global__ void sortprep_kernel(const float* __restrict__ boxes,
                                const int* __restrict__ labels) {
    const int b   = blockIdx.x;
    const int tid = threadIdx.x;
    __shared__ float  s_area[N_];
    __shared__ float4 s_sb[N_];

    float4 w0;
    int lab0 = 0;
    if (tid < N_) {
        const float* bx = boxes + ((size_t)b * N_ + tid) * 4;
        w0 = make_float4(bx[0], bx[1], bx[2], bx[3]);
        lab0 = labels[(size_t)b * N_ + tid];
        s_area[tid] = (w0.z - w0.x) * (w0.w - w0.y);
    }
    __syncthreads();
    if (tid < N_) {
        float a = s_area[tid];
        int rank = 0;
#pragma unroll
        for (int j = 0; j < N_; j++) {
            float aj = s_area[j];
            rank += (aj > a) || (aj == a && j < tid);   // stable descending
        }
        s_sb[rank]          = w0;
        g_sboxes[b][rank]   = w0;
        g_slabels[b][rank]  = lab0;
    }
    __syncthreads();

    // per-row masks: thread -> (lev, y); 248 rows total
    if (tid < 248) {
        int lev, y;
        if      (tid < 128) { lev = 0; y = tid; }
        else if (tid < 192) { lev = 1; y = tid - 128; }
        else if (tid < 224) { lev = 2; y = tid - 192; }
        else if (tid < 240) { lev = 3; y = tid - 224; }
        else                { lev = 4; y = tid - 240; }

        const int   H     = c_H[lev];
        const float ps    = c_ps[lev];
        const float invps = c_invps[lev];
        const float t0m   = c_th0[lev] * 0.999f;
        const float t1m   = c_th1[lev] * 1.001f;
        const float my    = ((float)y + 0.5f) * ps;

        unsigned long long cv0 = 0ull, cv1 = 0ull, cand = 0ull;
#pragma unroll 4
        for (int n = 0; n < N_; n++) {
            float4 w = s_sb[n];
            if (my >= w.y && my <= w.w) {
                float md = fmaxf(w.z - w.x, w.w - w.y);
                if (md > t0m && 0.5f * md <= t1m) cand |= 1ull << n;

                // exact x-coverage range: x s.t. (x+0.5)*ps in [w.x, w.z]
                int xlo = (int)ceilf(w.x * invps - 0.5f);
                if (((float)(xlo - 1) + 0.5f) * ps >= w.x) xlo--;
                else if (((float)xlo + 0.5f) * ps < w.x)  xlo++;
                int xhi = (int)floorf(w.z * invps - 0.5f);
                if (((float)(xhi + 1) + 0.5f) * ps <= w.z) xhi++;
                else if (((float)xhi + 0.5f) * ps > w.z)   xhi--;
                if (xlo < 0) xlo = 0;
                if (xhi > H - 1) xhi = H - 1;
                if (xlo <= xhi) {
                    int l0 = xlo < 64 ? xlo : 64;
                    int h0 = (xhi + 1) < 64 ? (xhi + 1) : 64;
                    if (h0 > l0)
                        cv0 |= ((h0 == 64) ? ~0ull : ((1ull << h0) - 1)) & ~((1ull << l0) - 1);
                    int l1 = xlo - 64 > 0 ? xlo - 64 : 0;
                    int h1 = xhi + 1 - 64 > 0 ? xhi + 1 - 64 : 0;
                    if (h1 > l1)
                        cv1 |= ((h1 == 64) ? ~0ull : ((1ull << h1) - 1)) & ~((1ull << l1) - 1);
                }
            }
        }
        g_cov[b][lev][y][0] = cv0;
        g_cov[b][lev][y][1] = cv1;
        g_cand[b][lev][y]   = cand;
    }
}

// ---------------- K2: bulk zero fill ----------------
__global__ __launch_bounds__(256)
void zero_kernel(float4* __restrict__ out, int n4) {
    int i = blockIdx.x * blockDim.x + threadIdx.x;
    const int stride = gridDim.x * blockDim.x;
    const float4 z = make_float4(0.0f, 0.0f, 0.0f, 0.0f);
    for (; i < n4; i += stride) out[i] = z;
}

// ---------------- K3: sparse value writer (2 pixels per thread) ----------------
__global__ __launch_bounds__(256)
void map_kernel(float* __restrict__ out) {
    const int b = blockIdx.y;
    __shared__ float4 sb[N_];
    __shared__ int    sl[N_];
    if (threadIdx.x < N_) {
        sb[threadIdx.x] = g_sboxes[b][threadIdx.x];
        sl[threadIdx.x] = g_slabels[b][threadIdx.x];
    }
    __syncthreads();

    const int gi = blockIdx.x * 256 + threadIdx.x;
    if (gi >= TOTAL_G2) return;
    const int lev = gi < 8192 ? 0 : gi < 10240 ? 1 : gi < 10752 ? 2 : gi < 10880 ? 3 : 4;
    const int g   = gi - c_gbase2[lev];

    const int   H   = c_H[lev];
    const int   HH  = H * H;
    const float ps  = c_ps[lev];
    const float th0 = c_th0[lev];
    const float th1 = c_th1[lev];

    const int gx2 = g << 1;
    const int y   = gx2 >> c_logH[lev];
    const int x0  = gx2 & (H - 1);
    const float my  = ((float)y + 0.5f) * ps;
    const float mxa = ((float)x0 + 0.5f) * ps;
    const float mxb = ((float)x0 + 1.5f) * ps;

    unsigned long long cand = g_cand[b][lev][y];
    const unsigned long long cov = g_cov[b][lev][y][x0 >> 6];
    const int sh = x0 & 63;

    int wa = -1, wb = -1;
    while (cand) {
        const int n = __ffsll(cand) - 1;
        cand &= cand - 1;
        float4 w = sb[n];
        float t  = my - w.y;     // >= 0 guaranteed by row mask
        float bo = w.w - my;     // >= 0 guaranteed by row mask
        float tbx = fmaxf(t, bo);
        {
            float l = mxa - w.x, r = w.z - mxa;
            float mxv = fmaxf(fmaxf(l, r), tbx);
            if (fminf(l, r) >= 0.0f && mxv > th0 && mxv <= th1) wa = n;
        }
        {
            float l = mxb - w.x, r = w.z - mxb;
            float mxv = fmaxf(fmaxf(l, r), tbx);
            if (fminf(l, r) >= 0.0f && mxv > th0 && mxv <= th1) wb = n;
        }
    }

    float* rowp = out + c_base[lev] + (size_t)b * C_ * HH + (size_t)y * H + x0;
    const size_t cs = (size_t)HH;
    float* clsp = rowp + 5 * cs;

    if (wa >= 0 || wb >= 0) {           // FIX: was (wa | wb) >= 0 (wrong for -1)
        float rl[2] = {0, 0}, rt[2] = {0, 0}, rr_[2] = {0, 0}, rb[2] = {0, 0}, ce[2] = {0, 0};
        const int   wn[2] = {wa, wb};
        const float mx[2] = {mxa, mxb};
#pragma unroll
        for (int k = 0; k < 2; k++) {
            if (wn[k] >= 0) {
                float4 w = sb[wn[k]];
                float l  = mx[k] - w.x;
                float t  = my    - w.y;
                float r  = w.z - mx[k];
                float bo = w.w - my;
                rl[k] = l; rt[k] = t; rr_[k] = r; rb[k] = bo;
                float dx = fminf(l, r),  Dx = fmaxf(l, r);
                float dy = fminf(t, bo), Dy = fmaxf(t, bo);
                float arg = (dx / (Dx != 0.0f ? Dx : 1.0f)) *
                            (dy / (Dy != 0.0f ? Dy : 1.0f));
                ce[k] = (arg > 0.0f) ? sqrtf(arg) : 0.0f;
            }
        }
        *reinterpret_cast<float2*>(rowp + 0 * cs) = make_float2(rl[0], rl[1]);
        *reinterpret_cast<float2*>(rowp + 1 * cs) = make_float2(rt[0], rt[1]);
        *reinterpret_cast<float2*>(rowp + 2 * cs) = make_float2(rr_[0], rr_[1]);
        *reinterpret_cast<float2*>(rowp + 3 * cs) = make_float2(rb[0], rb[1]);
        *reinterpret_cast<float2*>(rowp + 4 * cs) = make_float2(ce[0], ce[1]);
    }

    // class patches: one-hot for winners, background(ch0) where not covered
    if (wa >= 0)                          clsp[(size_t)sl[wa] * cs + 0] = 1.0f;
    else if (!((cov >> (sh + 0)) & 1ull)) clsp[0] = 1.0f;
    if (wb >= 0)                          clsp[(size_t)sl[wb] * cs + 1] = 1.0f;
    else if (!((cov >> (sh + 1)) & 1ull)) clsp[1] = 1.0f;
}

extern "C" void kernel_launch(void* const* d_in, const int* in_sizes, int n_in,
                              void* d_out, int out_size) {
    const float* boxes  = (const float*)d_in[0];
    const int*   labels = (const int*)d_in[1];
    float* out = (float*)d_out;

    const int n4 = out_size / 4;
    zero_kernel<<<1480, 256>>>((float4*)d_out, n4);

    sortprep_kernel<<<B_, 256>>>(boxes, labels);

    dim3 grid((TOTAL_G2 + 255) / 256, B_);   // 43 x 8
    map_kernel<<<grid, 256>>>(out);
}

// round 6
// speedup vs baseline: 1.0010x; 1.0010x over previous
#include <cuda_runtime.h>
#include <cstdint>

#define B_   8
#define N_   64
#define NUM_CLASSES 81
#define C_   86
#define NLEV 5
#define UNITS_PER_B 21824   // sum over levels of (HH/4)*4 slices

__constant__ int   c_H[NLEV]      = {128, 64, 32, 16, 8};
__constant__ int   c_logH[NLEV]   = {7, 6, 5, 4, 3};
__constant__ int   c_gshift4[NLEV]= {12, 10, 8, 6, 4};   // log2(HH/4)
__constant__ float c_ps[NLEV]     = {0.0078125f, 0.015625f, 0.03125f, 0.0625f, 0.125f};
__constant__ float c_invps[NLEV]  = {128.0f, 64.0f, 32.0f, 16.0f, 8.0f};
__constant__ float c_th0[NLEV]    = {0.0078125f, 0.0625f, 0.125f, 0.25f, 0.5f};
__constant__ float c_th1[NLEV]    = {0.0625f, 0.125f, 0.25f, 0.5f, 1.0f};
__constant__ size_t c_base[NLEV]  = {0ull, 11272192ull, 14090240ull, 14794752ull, 14970880ull};
__constant__ int   c_ubase[NLEV]  = {0, 16384, 20480, 21504, 21760};

// scratch (no allocation allowed)
__device__ float4             g_sboxes[B_][N_];
__device__ int                g_slabels[B_][N_];
__device__ unsigned long long g_cov[B_][NLEV][128][2];  // fg_any bitmask per row
__device__ unsigned long long g_cand[B_][NLEV][128];    // candidate boxes per row

// ---------------- K1: sort + per-row masks (validated R5) ----------------
__global__ void sortprep_kernel(const float* __restrict__ boxes,
                                const int* __restrict__ labels) {
    const int b   = blockIdx.x;
    const int tid = threadIdx.x;
    __shared__ float  s_area[N_];
    __shared__ float4 s_sb[N_];

    float4 w0;
    int lab0 = 0;
    if (tid < N_) {
        const float* bx = boxes + ((size_t)b * N_ + tid) * 4;
        w0 = make_float4(bx[0], bx[1], bx[2], bx[3]);
        lab0 = labels[(size_t)b * N_ + tid];
        s_area[tid] = (w0.z - w0.x) * (w0.w - w0.y);
    }
    __syncthreads();
    if (tid < N_) {
        float a = s_area[tid];
        int rank = 0;
#pragma unroll
        for (int j = 0; j < N_; j++) {
            float aj = s_area[j];
            rank += (aj > a) || (aj == a && j < tid);
        }
        s_sb[rank]         = w0;
        g_sboxes[b][rank]  = w0;
        g_slabels[b][rank] = lab0;
    }
    __syncthreads();

    if (tid < 248) {
        int lev, y;
        if      (tid < 128) { lev = 0; y = tid; }
        else if (tid < 192) { lev = 1; y = tid - 128; }
        else if (tid < 224) { lev = 2; y = tid - 192; }
        else if (tid < 240) { lev = 3; y = tid - 224; }
        else                { lev = 4; y = tid - 240; }

        const int   H     = c_H[lev];
        const float ps    = c_ps[lev];
        const float invps = c_invps[lev];
        const float t0m   = c_th0[lev] * 0.999f;
        const float t1m   = c_th1[lev] * 1.001f;
        const float my    = ((float)y + 0.5f) * ps;

        unsigned long long cv0 = 0ull, cv1 = 0ull, cand = 0ull;
#pragma unroll 4
        for (int n = 0; n < N_; n++) {
            float4 w = s_sb[n];
            if (my >= w.y && my <= w.w) {
                float md = fmaxf(w.z - w.x, w.w - w.y);
                if (md > t0m && 0.5f * md <= t1m) cand |= 1ull << n;

                int xlo = (int)ceilf(w.x * invps - 0.5f);
                if (((float)(xlo - 1) + 0.5f) * ps >= w.x) xlo--;
                else if (((float)xlo + 0.5f) * ps < w.x)  xlo++;
                int xhi = (int)floorf(w.z * invps - 0.5f);
                if (((float)(xhi + 1) + 0.5f) * ps <= w.z) xhi++;
                else if (((float)xhi + 0.5f) * ps > w.z)   xhi--;
                if (xlo < 0) xlo = 0;
                if (xhi > H - 1) xhi = H - 1;
                if (xlo <= xhi) {
                    int l0 = xlo < 64 ? xlo : 64;
                    int h0 = (xhi + 1) < 64 ? (xhi + 1) : 64;
                    if (h0 > l0)
                        cv0 |= ((h0 == 64) ? ~0ull : ((1ull << h0) - 1)) & ~((1ull << l0) - 1);
                    int l1 = xlo - 64 > 0 ? xlo - 64 : 0;
                    int h1 = xhi + 1 - 64 > 0 ? xhi + 1 - 64 : 0;
                    if (h1 > l1)
                        cv1 |= ((h1 == 64) ? ~0ull : ((1ull << h1) - 1)) & ~((1ull << l1) - 1);
                }
            }
        }
        g_cov[b][lev][y][0] = cv0;
        g_cov[b][lev][y][1] = cv1;
        g_cand[b][lev][y]   = cand;
    }
}

// ---------------- K2: fused zero + value writer ----------------
// unit = (lev, slice, 4-pixel group). Each thread writes ~22 float4 channels.
__global__ __launch_bounds__(256)
void fused_kernel(float* __restrict__ out) {
    const int b = blockIdx.y;
    __shared__ float4 sb[N_];
    __shared__ int    sl[N_];
    if (threadIdx.x < N_) {
        sb[threadIdx.x] = g_sboxes[b][threadIdx.x];
        sl[threadIdx.x] = g_slabels[b][threadIdx.x];
    }
    __syncthreads();

    const int u = blockIdx.x * 256 + threadIdx.x;
    if (u >= UNITS_PER_B) return;
    const int lev = u < 16384 ? 0 : u < 20480 ? 1 : u < 21504 ? 2 : u < 21760 ? 3 : 4;
    const int local = u - c_ubase[lev];
    const int gsh   = c_gshift4[lev];
    const int s     = local >> gsh;            // channel slice 0..3
    const int g     = local & ((1 << gsh) - 1);

    const int   H   = c_H[lev];
    const int   HH  = H * H;
    const float ps  = c_ps[lev];
    const float th0 = c_th0[lev];
    const float th1 = c_th1[lev];

    const int gx4 = g << 2;
    const int y   = gx4 >> c_logH[lev];
    const int x0  = gx4 & (H - 1);
    const float my = ((float)y + 0.5f) * ps;
    float mx[4];
#pragma unroll
    for (int k = 0; k < 4; k++) mx[k] = ((float)(x0 + k) + 0.5f) * ps;

    // winners via row candidate mask (typically 0-2 set bits)
    unsigned long long cand = g_cand[b][lev][y];
    int win[4] = {-1, -1, -1, -1};
    while (cand) {
        const int n = __ffsll(cand) - 1;
        cand &= cand - 1;
        float4 w = sb[n];
        float t   = my - w.y;   // >= 0 by row mask
        float bo  = w.w - my;   // >= 0 by row mask
        float tbx = fmaxf(t, bo);
#pragma unroll
        for (int k = 0; k < 4; k++) {
            float l = mx[k] - w.x, r = w.z - mx[k];
            float mxv = fmaxf(fmaxf(l, r), tbx);
            if (fminf(l, r) >= 0.0f && mxv > th0 && mxv <= th1) win[k] = n;
        }
    }

    int  lab[4];
    bool hw[4];
#pragma unroll
    for (int k = 0; k < 4; k++) {
        hw[k]  = (win[k] >= 0);
        lab[k] = hw[k] ? sl[win[k]] : -1;
    }

    float* rowp = out + c_base[lev] + (size_t)b * C_ * HH + (size_t)y * H + x0;
    const size_t cs = (size_t)HH;
    float* clsp = rowp + 5 * cs;
    const float4 z = make_float4(0.0f, 0.0f, 0.0f, 0.0f);

    if (s == 0) {
        // reg + centerness
        float rl[4], rt[4], rr_[4], rb[4], ce[4];
#pragma unroll
        for (int k = 0; k < 4; k++) {
            if (hw[k]) {
                float4 w = sb[win[k]];
                float l  = mx[k] - w.x;
                float t  = my    - w.y;
                float r  = w.z - mx[k];
                float bo = w.w - my;
                rl[k] = l; rt[k] = t; rr_[k] = r; rb[k] = bo;
                float dx = fminf(l, r),  Dx = fmaxf(l, r);
                float dy = fminf(t, bo), Dy = fmaxf(t, bo);
                float arg = (dx / (Dx != 0.0f ? Dx : 1.0f)) *
                            (dy / (Dy != 0.0f ? Dy : 1.0f));
                ce[k] = (arg > 0.0f) ? sqrtf(arg) : 0.0f;
            } else {
                rl[k] = rt[k] = rr_[k] = rb[k] = 0.0f;
                ce[k] = 0.0f;
            }
        }
        *reinterpret_cast<float4*>(rowp + 0 * cs) = make_float4(rl[0], rl[1], rl[2], rl[3]);
        *reinterpret_cast<float4*>(rowp + 1 * cs) = make_float4(rt[0], rt[1], rt[2], rt[3]);
        *reinterpret_cast<float4*>(rowp + 2 * cs) = make_float4(rr_[0], rr_[1], rr_[2], rr_[3]);
        *reinterpret_cast<float4*>(rowp + 3 * cs) = make_float4(rb[0], rb[1], rb[2], rb[3]);
        *reinterpret_cast<float4*>(rowp + 4 * cs) = make_float4(ce[0], ce[1], ce[2], ce[3]);

        // class channels 0..16: zero then patch
#pragma unroll 17
        for (int cc = 0; cc < 17; cc++)
            *reinterpret_cast<float4*>(clsp + (size_t)cc * cs) = z;

        const unsigned long long cov = g_cov[b][lev][y][x0 >> 6];
        const int sh = x0 & 63;   // x0 is 4-aligned -> sh <= 60, 4 bits in one word
#pragma unroll
        for (int k = 0; k < 4; k++) {
            if (hw[k]) { if (lab[k] < 17) clsp[(size_t)lab[k] * cs + k] = 1.0f; }
            else if (!((cov >> (sh + k)) & 1ull)) clsp[k] = 1.0f;   // background
        }
    } else {
        const int lo = 17 + (s - 1) * 22;
        const int hi = (s == 3) ? NUM_CLASSES : lo + 22;
#pragma unroll 11
        for (int cc = lo; cc < hi; cc++)
            *reinterpret_cast<float4*>(clsp + (size_t)cc * cs) = z;
#pragma unroll
        for (int k = 0; k < 4; k++)
            if (hw[k] && lab[k] >= lo && lab[k] < hi)
                clsp[(size_t)lab[k] * cs + k] = 1.0f;
    }
}

extern "C" void kernel_launch(void* const* d_in, const int* in_sizes, int n_in,
                              void* d_out, int out_size) {
    const float* boxes  = (const float*)d_in[0];
    const int*   labels = (const int*)d_in[1];
    float* out = (float*)d_out;

    sortprep_kernel<<<B_, 256>>>(boxes, labels);

    dim3 grid((UNITS_PER_B + 255) / 256, B_);   // 86 x 8
    fused_kernel<<<grid, 256>>>(out);
}

// round 7
// speedup vs baseline: 1.2369x; 1.2357x over previous
#include <cuda_runtime.h>
#include <cstdint>

#define B_   8
#define N_   64
#define NUM_CLASSES 81
#define C_   86
#define NLEV 5
#define UNITS_PER_B 21824
#define NROWS 248            // rows per batch across levels

__constant__ int   c_H[NLEV]      = {128, 64, 32, 16, 8};
__constant__ int   c_logH[NLEV]   = {7, 6, 5, 4, 3};
__constant__ int   c_gshift4[NLEV]= {12, 10, 8, 6, 4};
__constant__ float c_ps[NLEV]     = {0.0078125f, 0.015625f, 0.03125f, 0.0625f, 0.125f};
__constant__ float c_invps[NLEV]  = {128.0f, 64.0f, 32.0f, 16.0f, 8.0f};
__constant__ float c_th0[NLEV]    = {0.0078125f, 0.0625f, 0.125f, 0.25f, 0.5f};
__constant__ float c_th1[NLEV]    = {0.0625f, 0.125f, 0.25f, 0.5f, 1.0f};
__constant__ size_t c_base[NLEV]  = {0ull, 11272192ull, 14090240ull, 14794752ull, 14970880ull};
__constant__ int   c_ubase[NLEV]  = {0, 16384, 20480, 21504, 21760};

// scratch (no allocation allowed)
__device__ float4             g_sboxes[B_][N_];
__device__ int                g_slabels[B_][N_];
__device__ unsigned long long g_cov[B_][NLEV][128][2];
__device__ unsigned long long g_cand[B_][NLEV][128];

// ---------------- K1: stable descending-area sort (tiny) ----------------
__global__ void sort_kernel(const float* __restrict__ boxes,
                            const int* __restrict__ labels) {
    const int b = blockIdx.x;
    const int i = threadIdx.x;   // 64 threads
    __shared__ float s_area[N_];

    const float* bx = boxes + ((size_t)b * N_ + i) * 4;
    float4 w = make_float4(bx[0], bx[1], bx[2], bx[3]);
    s_area[i] = (w.z - w.x) * (w.w - w.y);
    __syncthreads();

    float a = s_area[i];
    int rank = 0;
#pragma unroll
    for (int j = 0; j < N_; j++) {
        float aj = s_area[j];
        rank += (aj > a) || (aj == a && j < i);
    }
    g_sboxes[b][rank]  = w;
    g_slabels[b][rank] = labels[(size_t)b * N_ + i];
}

// ---------------- K2: per-row masks, one warp per row ----------------
__global__ __launch_bounds__(256)
void rowmask_kernel() {
    const int wglob = (blockIdx.x * 256 + threadIdx.x) >> 5;
    const int lane  = threadIdx.x & 31;
    if (wglob >= B_ * NROWS) return;
    const int b   = wglob / NROWS;
    const int rid = wglob % NROWS;

    int lev, y;
    if      (rid < 128) { lev = 0; y = rid; }
    else if (rid < 192) { lev = 1; y = rid - 128; }
    else if (rid < 224) { lev = 2; y = rid - 192; }
    else if (rid < 240) { lev = 3; y = rid - 224; }
    else                { lev = 4; y = rid - 240; }

    const int   H     = c_H[lev];
    const float ps    = c_ps[lev];
    const float invps = c_invps[lev];
    const float t0m   = c_th0[lev] * 0.999f;
    const float t1m   = c_th1[lev] * 1.001f;
    const float my    = ((float)y + 0.5f) * ps;

    unsigned long long cv0 = 0ull, cv1 = 0ull, cand = 0ull;
#pragma unroll
    for (int t = 0; t < 2; t++) {
        const int n = lane + t * 32;
        float4 w = g_sboxes[b][n];
        if (my >= w.y && my <= w.w) {
            float md = fmaxf(w.z - w.x, w.w - w.y);
            if (md > t0m && 0.5f * md <= t1m) cand |= 1ull << n;

            // exact x-coverage: x s.t. (x+0.5)*ps in [w.x, w.z], with fixup
            int xlo = (int)ceilf(w.x * invps - 0.5f);
            if (((float)(xlo - 1) + 0.5f) * ps >= w.x) xlo--;
            else if (((float)xlo + 0.5f) * ps < w.x)  xlo++;
            int xhi = (int)floorf(w.z * invps - 0.5f);
            if (((float)(xhi + 1) + 0.5f) * ps <= w.z) xhi++;
            else if (((float)xhi + 0.5f) * ps > w.z)   xhi--;
            if (xlo < 0) xlo = 0;
            if (xhi > H - 1) xhi = H - 1;
            if (xlo <= xhi) {
                int l0 = xlo < 64 ? xlo : 64;
                int h0 = (xhi + 1) < 64 ? (xhi + 1) : 64;
                if (h0 > l0)
                    cv0 |= ((h0 == 64) ? ~0ull : ((1ull << h0) - 1)) & ~((1ull << l0) - 1);
                int l1 = xlo - 64 > 0 ? xlo - 64 : 0;
                int h1 = xhi + 1 - 64 > 0 ? xhi + 1 - 64 : 0;
                if (h1 > l1)
                    cv1 |= ((h1 == 64) ? ~0ull : ((1ull << h1) - 1)) & ~((1ull << l1) - 1);
            }
        }
    }
#pragma unroll
    for (int off = 16; off > 0; off >>= 1) {
        cv0  |= __shfl_xor_sync(0xFFFFFFFFu, cv0,  off);
        cv1  |= __shfl_xor_sync(0xFFFFFFFFu, cv1,  off);
        cand |= __shfl_xor_sync(0xFFFFFFFFu, cand, off);
    }
    if (lane == 0) {
        g_cov[b][lev][y][0] = cv0;
        g_cov[b][lev][y][1] = cv1;
        g_cand[b][lev][y]   = cand;
    }
}

// ---------------- K3: zeros-first fused writer ----------------
__global__ __launch_bounds__(256)
void fused_kernel(float* __restrict__ out) {
    const int b = blockIdx.y;
    const int u = blockIdx.x * 256 + threadIdx.x;
    if (u >= UNITS_PER_B) return;
    const int lev = u < 16384 ? 0 : u < 20480 ? 1 : u < 21504 ? 2 : u < 21760 ? 3 : 4;
    const int local = u - c_ubase[lev];
    const int gsh   = c_gshift4[lev];
    const int s     = local >> gsh;
    const int g     = local & ((1 << gsh) - 1);

    const int   H   = c_H[lev];
    const int   HH  = H * H;
    const float ps  = c_ps[lev];

    const int gx4 = g << 2;
    const int y   = gx4 >> c_logH[lev];
    const int x0  = gx4 & (H - 1);

    // kick off metadata loads first
    unsigned long long cand = g_cand[b][lev][y];
    const unsigned long long cov = g_cov[b][lev][y][x0 >> 6];

    float* rowp = out + c_base[lev] + (size_t)b * C_ * HH + (size_t)y * H + x0;
    const size_t cs = (size_t)HH;
    float* clsp = rowp + 5 * cs;
    const float4 z = make_float4(0.0f, 0.0f, 0.0f, 0.0f);

    // ---- phase 1: unconditional zero fill of this slice ----
    if (s == 0) {
#pragma unroll 22
        for (int ch = 0; ch < 22; ch++)          // ch0-4 reg/cent + cls0-16
            *reinterpret_cast<float4*>(rowp + (size_t)ch * cs) = z;
    } else {
        const int lo = 17 + (s - 1) * 22;
        const int hi = (s == 3) ? NUM_CLASSES : lo + 22;
#pragma unroll 11
        for (int cc = lo; cc < hi; cc++)
            *reinterpret_cast<float4*>(clsp + (size_t)cc * cs) = z;
    }

    // ---- phase 2: sparse values / patches ----
    const int sh = x0 & 63;
    if (cand == 0ull) {
        if (s == 0) {
#pragma unroll
            for (int k = 0; k < 4; k++)
                if (!((cov >> (sh + k)) & 1ull)) clsp[k] = 1.0f;   // background
        }
        return;
    }

    const float th0 = c_th0[lev];
    const float th1 = c_th1[lev];
    const float my = ((float)y + 0.5f) * ps;
    float mx[4];
#pragma unroll
    for (int k = 0; k < 4; k++) mx[k] = ((float)(x0 + k) + 0.5f) * ps;

    int win[4] = {-1, -1, -1, -1};
    while (cand) {
        const int n = __ffsll(cand) - 1;
        cand &= cand - 1;
        float4 w = g_sboxes[b][n];
        float t   = my - w.y;
        float bo  = w.w - my;
        float tbx = fmaxf(t, bo);
#pragma unroll
        for (int k = 0; k < 4; k++) {
            float l = mx[k] - w.x, r = w.z - mx[k];
            float mxv = fmaxf(fmaxf(l, r), tbx);
            if (fminf(l, r) >= 0.0f && mxv > th0 && mxv <= th1) win[k] = n;
        }
    }

    if (s == 0) {
        bool anyw = (win[0] >= 0) || (win[1] >= 0) || (win[2] >= 0) || (win[3] >= 0);
        if (anyw) {
            float rl[4], rt[4], rr_[4], rb[4], ce[4];
#pragma unroll
            for (int k = 0; k < 4; k++) {
                if (win[k] >= 0) {
                    float4 w = g_sboxes[b][win[k]];
                    float l  = mx[k] - w.x;
                    float t  = my    - w.y;
                    float r  = w.z - mx[k];
                    float bo = w.w - my;
                    rl[k] = l; rt[k] = t; rr_[k] = r; rb[k] = bo;
                    float dx = fminf(l, r),  Dx = fmaxf(l, r);
                    float dy = fminf(t, bo), Dy = fmaxf(t, bo);
                    float arg = (dx / (Dx != 0.0f ? Dx : 1.0f)) *
                                (dy / (Dy != 0.0f ? Dy : 1.0f));
                    ce[k] = (arg > 0.0f) ? sqrtf(arg) : 0.0f;
                } else {
                    rl[k] = rt[k] = rr_[k] = rb[k] = 0.0f;
                    ce[k] = 0.0f;
                }
            }
            *reinterpret_cast<float4*>(rowp + 0 * cs) = make_float4(rl[0], rl[1], rl[2], rl[3]);
            *reinterpret_cast<float4*>(rowp + 1 * cs) = make_float4(rt[0], rt[1], rt[2], rt[3]);
            *reinterpret_cast<float4*>(rowp + 2 * cs) = make_float4(rr_[0], rr_[1], rr_[2], rr_[3]);
            *reinterpret_cast<float4*>(rowp + 3 * cs) = make_float4(rb[0], rb[1], rb[2], rb[3]);
            *reinterpret_cast<float4*>(rowp + 4 * cs) = make_float4(ce[0], ce[1], ce[2], ce[3]);
        }
#pragma unroll
        for (int k = 0; k < 4; k++) {
            if (win[k] >= 0) {
                int lab = g_slabels[b][win[k]];
                if (lab < 17) clsp[(size_t)lab * cs + k] = 1.0f;
            } else if (!((cov >> (sh + k)) & 1ull)) {
                clsp[k] = 1.0f;
            }
        }
    } else {
        const int lo = 17 + (s - 1) * 22;
        const int hi = (s == 3) ? NUM_CLASSES : lo + 22;
#pragma unroll
        for (int k = 0; k < 4; k++) {
            if (win[k] >= 0) {
                int lab = g_slabels[b][win[k]];
                if (lab >= lo && lab < hi) clsp[(size_t)lab * cs + k] = 1.0f;
            }
        }
    }
}

extern "C" void kernel_launch(void* const* d_in, const int* in_sizes, int n_in,
                              void* d_out, int out_size) {
    const float* boxes  = (const float*)d_in[0];
    const int*   labels = (const int*)d_in[1];
    float* out = (float*)d_out;

    sort_kernel<<<B_, N_>>>(boxes, labels);
    rowmask_kernel<<<(B_ * NROWS * 32 + 255) / 256, 256>>>();   // 248 blocks

    dim3 grid((UNITS_PER_B + 255) / 256, B_);   // 86 x 8
    fused_kernel<<<grid, 256>>>(out);
}

// round 8
// speedup vs baseline: 1.2833x; 1.0375x over previous
#include <cuda_runtime.h>
#include <cstdint>

#define B_   8
#define N_   64
#define NUM_CLASSES 81
#define C_   86
#define NLEV 5
#define UNITS_PER_B 21824
#define NROWS 248

__constant__ int   c_H[NLEV]      = {128, 64, 32, 16, 8};
__constant__ int   c_logH[NLEV]   = {7, 6, 5, 4, 3};
__constant__ int   c_gshift4[NLEV]= {12, 10, 8, 6, 4};
__constant__ float c_ps[NLEV]     = {0.0078125f, 0.015625f, 0.03125f, 0.0625f, 0.125f};
__constant__ float c_invps[NLEV]  = {128.0f, 64.0f, 32.0f, 16.0f, 8.0f};
__constant__ float c_th0[NLEV]    = {0.0078125f, 0.0625f, 0.125f, 0.25f, 0.5f};
__constant__ float c_th1[NLEV]    = {0.0625f, 0.125f, 0.25f, 0.5f, 1.0f};
__constant__ size_t c_base[NLEV]  = {0ull, 11272192ull, 14090240ull, 14794752ull, 14970880ull};
__constant__ int   c_ubase[NLEV]  = {0, 16384, 20480, 21504, 21760};
// block -> level (86 blocks per batch, exactly level-aligned)
__constant__ unsigned char c_blklev[86] = {
    0,0,0,0,0,0,0,0,0,0,0,0,0,0,0,0,0,0,0,0,0,0,0,0,0,0,0,0,0,0,0,0,
    0,0,0,0,0,0,0,0,0,0,0,0,0,0,0,0,0,0,0,0,0,0,0,0,0,0,0,0,0,0,0,0,
    1,1,1,1,1,1,1,1,1,1,1,1,1,1,1,1,
    2,2,2,2,
    3,
    4
};

// scratch (no allocation allowed)
__device__ float4             g_sboxes[B_][N_];
__device__ int                g_slabels[B_][N_];
__device__ unsigned long long g_cov[B_][NLEV][128][2];
__device__ unsigned long long g_cand[B_][NLEV][128];

// ---------------- K1: fused sort + per-row masks ----------------
// grid (31, B_), 256 threads. Each block sorts (redundantly, in smem) then
// its 8 warps produce masks for rows [blockIdx.x*8, +8).
__global__ __launch_bounds__(256)
void prep_kernel(const float* __restrict__ boxes,
                 const int* __restrict__ labels) {
    const int b   = blockIdx.y;
    const int tid = threadIdx.x;
    __shared__ float  s_area[N_];
    __shared__ float4 s_sb[N_];
    __shared__ int    s_sl[N_];

    float4 w0;
    int lab0 = 0;
    if (tid < N_) {
        const float* bx = boxes + ((size_t)b * N_ + tid) * 4;
        w0 = make_float4(bx[0], bx[1], bx[2], bx[3]);
        lab0 = labels[(size_t)b * N_ + tid];
        s_area[tid] = (w0.z - w0.x) * (w0.w - w0.y);
    }
    __syncthreads();
    if (tid < N_) {
        float a = s_area[tid];
        int rank = 0;
#pragma unroll
        for (int j = 0; j < N_; j++) {
            float aj = s_area[j];
            rank += (aj > a) || (aj == a && j < tid);   // stable descending
        }
        s_sb[rank] = w0;
        s_sl[rank] = lab0;
    }
    __syncthreads();

    // block 0 publishes sorted arrays for the writer kernel
    if (blockIdx.x == 0 && tid < N_) {
        g_sboxes[b][tid]  = s_sb[tid];
        g_slabels[b][tid] = s_sl[tid];
    }

    const int lane = tid & 31;
    const int rid  = blockIdx.x * 8 + (tid >> 5);
    if (rid >= NROWS) return;

    int lev, y;
    if      (rid < 128) { lev = 0; y = rid; }
    else if (rid < 192) { lev = 1; y = rid - 128; }
    else if (rid < 224) { lev = 2; y = rid - 192; }
    else if (rid < 240) { lev = 3; y = rid - 224; }
    else                { lev = 4; y = rid - 240; }

    const int   H     = c_H[lev];
    const float ps    = c_ps[lev];
    const float invps = c_invps[lev];
    const float t0m   = c_th0[lev] * 0.999f;
    const float t1m   = c_th1[lev] * 1.001f;
    const float my    = ((float)y + 0.5f) * ps;

    unsigned long long cv0 = 0ull, cv1 = 0ull, cand = 0ull;
#pragma unroll
    for (int t = 0; t < 2; t++) {
        const int n = lane + t * 32;
        float4 w = s_sb[n];
        if (my >= w.y && my <= w.w) {
            float md = fmaxf(w.z - w.x, w.w - w.y);
            if (md > t0m && 0.5f * md <= t1m) cand |= 1ull << n;

            // exact x-coverage: x s.t. (x+0.5)*ps in [w.x, w.z], with fixup
            int xlo = (int)ceilf(w.x * invps - 0.5f);
            if (((float)(xlo - 1) + 0.5f) * ps >= w.x) xlo--;
            else if (((float)xlo + 0.5f) * ps < w.x)  xlo++;
            int xhi = (int)floorf(w.z * invps - 0.5f);
            if (((float)(xhi + 1) + 0.5f) * ps <= w.z) xhi++;
            else if (((float)xhi + 0.5f) * ps > w.z)   xhi--;
            if (xlo < 0) xlo = 0;
            if (xhi > H - 1) xhi = H - 1;
            if (xlo <= xhi) {
                int l0 = xlo < 64 ? xlo : 64;
                int h0 = (xhi + 1) < 64 ? (xhi + 1) : 64;
                if (h0 > l0)
                    cv0 |= ((h0 == 64) ? ~0ull : ((1ull << h0) - 1)) & ~((1ull << l0) - 1);
                int l1 = xlo - 64 > 0 ? xlo - 64 : 0;
                int h1 = xhi + 1 - 64 > 0 ? xhi + 1 - 64 : 0;
                if (h1 > l1)
                    cv1 |= ((h1 == 64) ? ~0ull : ((1ull << h1) - 1)) & ~((1ull << l1) - 1);
            }
        }
    }
#pragma unroll
    for (int off = 16; off > 0; off >>= 1) {
        cv0  |= __shfl_xor_sync(0xFFFFFFFFu, cv0,  off);
        cv1  |= __shfl_xor_sync(0xFFFFFFFFu, cv1,  off);
        cand |= __shfl_xor_sync(0xFFFFFFFFu, cand, off);
    }
    if (lane == 0) {
        g_cov[b][lev][y][0] = cv0;
        g_cov[b][lev][y][1] = cv1;
        g_cand[b][lev][y]   = cand;
    }
}

// ---------------- K2: zeros-first fused writer ----------------
__global__ __launch_bounds__(256)
void fused_kernel(float* __restrict__ out) {
    const int b   = blockIdx.y;
    const int lev = c_blklev[blockIdx.x];       // warp-uniform
    const int u   = blockIdx.x * 256 + threadIdx.x;
    const int local = u - c_ubase[lev];
    const int gsh   = c_gshift4[lev];
    if (local >= (4 << gsh)) return;            // only tail of lev4 block
    const int s = local >> gsh;
    const int g = local & ((1 << gsh) - 1);

    const int   H  = c_H[lev];
    const int   HH = H * H;

    const int gx4 = g << 2;
    const int y   = gx4 >> c_logH[lev];
    const int x0  = gx4 & (H - 1);

    // metadata loads first (overlap with zero stores)
    unsigned long long cand = g_cand[b][lev][y];
    const unsigned long long cov = (s == 0) ? g_cov[b][lev][y][x0 >> 6] : 0ull;

    float* rowp = out + c_base[lev] + (size_t)b * C_ * HH + (size_t)y * H + x0;
    const size_t cs = (size_t)HH;
    float* clsp = rowp + 5 * cs;
    const float4 z = make_float4(0.0f, 0.0f, 0.0f, 0.0f);

    // ---- phase 1: unconditional zero fill ----
    if (s == 0) {
#pragma unroll 22
        for (int ch = 0; ch < 22; ch++)
            *reinterpret_cast<float4*>(rowp + (size_t)ch * cs) = z;
    } else {
        const int lo = 17 + (s - 1) * 22;
        const int hi = (s == 3) ? NUM_CLASSES : lo + 22;
#pragma unroll 11
        for (int cc = lo; cc < hi; cc++)
            *reinterpret_cast<float4*>(clsp + (size_t)cc * cs) = z;
    }

    // ---- phase 2: sparse values / patches ----
    const int sh = x0 & 63;
    if (cand == 0ull) {
        if (s == 0) {
#pragma unroll
            for (int k = 0; k < 4; k++)
                if (!((cov >> (sh + k)) & 1ull)) clsp[k] = 1.0f;
        }
        return;
    }

    const float ps  = c_ps[lev];
    const float th0 = c_th0[lev];
    const float th1 = c_th1[lev];
    const float my = ((float)y + 0.5f) * ps;
    float mx[4];
#pragma unroll
    for (int k = 0; k < 4; k++) mx[k] = ((float)(x0 + k) + 0.5f) * ps;

    int win[4] = {-1, -1, -1, -1};
    while (cand) {
        const int n = __ffsll(cand) - 1;
        cand &= cand - 1;
        float4 w = g_sboxes[b][n];
        float t   = my - w.y;
        float bo  = w.w - my;
        float tbx = fmaxf(t, bo);
#pragma unroll
        for (int k = 0; k < 4; k++) {
            float l = mx[k] - w.x, r = w.z - mx[k];
            float mxv = fmaxf(fmaxf(l, r), tbx);
            if (fminf(l, r) >= 0.0f && mxv > th0 && mxv <= th1) win[k] = n;
        }
    }

    if (s == 0) {
        bool anyw = (win[0] >= 0) || (win[1] >= 0) || (win[2] >= 0) || (win[3] >= 0);
        if (anyw) {
            float rl[4], rt[4], rr_[4], rb[4], ce[4];
#pragma unroll
            for (int k = 0; k < 4; k++) {
                if (win[k] >= 0) {
                    float4 w = g_sboxes[b][win[k]];
                    float l  = mx[k] - w.x;
                    float t  = my    - w.y;
                    float r  = w.z - mx[k];
                    float bo = w.w - my;
                    rl[k] = l; rt[k] = t; rr_[k] = r; rb[k] = bo;
                    float dx = fminf(l, r),  Dx = fmaxf(l, r);
                    float dy = fminf(t, bo), Dy = fmaxf(t, bo);
                    float arg = (dx / (Dx != 0.0f ? Dx : 1.0f)) *
                                (dy / (Dy != 0.0f ? Dy : 1.0f));
                    ce[k] = (arg > 0.0f) ? sqrtf(arg) : 0.0f;
                } else {
                    rl[k] = rt[k] = rr_[k] = rb[k] = 0.0f;
                    ce[k] = 0.0f;
                }
            }
            *reinterpret_cast<float4*>(rowp + 0 * cs) = make_float4(rl[0], rl[1], rl[2], rl[3]);
            *reinterpret_cast<float4*>(rowp + 1 * cs) = make_float4(rt[0], rt[1], rt[2], rt[3]);
            *reinterpret_cast<float4*>(rowp + 2 * cs) = make_float4(rr_[0], rr_[1], rr_[2], rr_[3]);
            *reinterpret_cast<float4*>(rowp + 3 * cs) = make_float4(rb[0], rb[1], rb[2], rb[3]);
            *reinterpret_cast<float4*>(rowp + 4 * cs) = make_float4(ce[0], ce[1], ce[2], ce[3]);
        }
#pragma unroll
        for (int k = 0; k < 4; k++) {
            if (win[k] >= 0) {
                int lab = g_slabels[b][win[k]];
                if (lab < 17) clsp[(size_t)lab * cs + k] = 1.0f;
            } else if (!((cov >> (sh + k)) & 1ull)) {
                clsp[k] = 1.0f;
            }
        }
    } else {
        const int lo = 17 + (s - 1) * 22;
        const int hi = (s == 3) ? NUM_CLASSES : lo + 22;
#pragma unroll
        for (int k = 0; k < 4; k++) {
            if (win[k] >= 0) {
                int lab = g_slabels[b][win[k]];
                if (lab >= lo && lab < hi) clsp[(size_t)lab * cs + k] = 1.0f;
            }
        }
    }
}

extern "C" void kernel_launch(void* const* d_in, const int* in_sizes, int n_in,
                              void* d_out, int out_size) {
    const float* boxes  = (const float*)d_in[0];
    const int*   labels = (const int*)d_in[1];
    float* out = (float*)d_out;

    dim3 pgrid(31, B_);                 // 248 blocks: sort + masks
    prep_kernel<<<pgrid, 256>>>(boxes, labels);

    dim3 grid(86, B_);
    fused_kernel<<<grid, 256>>>(out);
}

// round 9
// speedup vs baseline: 1.3759x; 1.0721x over previous
#include <cuda_runtime.h>
#include <cstdint>

#define B_   8
#define N_   64
#define NUM_CLASSES 81
#define C_   86
#define NLEV 5
#define NROWS 248
#define UNITS8_PER_B 43648   // 8 slices x (HH/4) summed over levels

__constant__ int   c_H[NLEV]      = {128, 64, 32, 16, 8};
__constant__ int   c_logH[NLEV]   = {7, 6, 5, 4, 3};
__constant__ int   c_gshift4[NLEV]= {12, 10, 8, 6, 4};   // log2(HH/4)
__constant__ float c_ps[NLEV]     = {0.0078125f, 0.015625f, 0.03125f, 0.0625f, 0.125f};
__constant__ float c_invps[NLEV]  = {128.0f, 64.0f, 32.0f, 16.0f, 8.0f};
__constant__ float c_th0[NLEV]    = {0.0078125f, 0.0625f, 0.125f, 0.25f, 0.5f};
__constant__ float c_th1[NLEV]    = {0.0625f, 0.125f, 0.25f, 0.5f, 1.0f};
__constant__ size_t c_base[NLEV]  = {0ull, 11272192ull, 14090240ull, 14794752ull, 14970880ull};
__constant__ int   c_ubase[NLEV]  = {0, 32768, 40960, 43008, 43520};
// block -> level (171 blocks per batch; lev0:0-127, lev1:128-159, lev2:160-167,
// lev3:168-169, lev4:170)
__constant__ unsigned char c_blklev[171] = {
    0,0,0,0,0,0,0,0,0,0,0,0,0,0,0,0,0,0,0,0,0,0,0,0,0,0,0,0,0,0,0,0,
    0,0,0,0,0,0,0,0,0,0,0,0,0,0,0,0,0,0,0,0,0,0,0,0,0,0,0,0,0,0,0,0,
    0,0,0,0,0,0,0,0,0,0,0,0,0,0,0,0,0,0,0,0,0,0,0,0,0,0,0,0,0,0,0,0,
    0,0,0,0,0,0,0,0,0,0,0,0,0,0,0,0,0,0,0,0,0,0,0,0,0,0,0,0,0,0,0,0,
    1,1,1,1,1,1,1,1,1,1,1,1,1,1,1,1,1,1,1,1,1,1,1,1,1,1,1,1,1,1,1,1,
    2,2,2,2,2,2,2,2,
    3,3,
    4
};

// scratch (no allocation allowed)
__device__ float4             g_sboxes[B_][N_];
__device__ int                g_slabels[B_][N_];
__device__ unsigned long long g_cov[B_][NLEV][128][2];
__device__ unsigned long long g_cand[B_][NLEV][128];

// ---------------- K1: fused sort + per-row masks (validated R8) ----------------
__global__ __launch_bounds__(256)
void prep_kernel(const float* __restrict__ boxes,
                 const int* __restrict__ labels) {
    const int b   = blockIdx.y;
    const int tid = threadIdx.x;
    __shared__ float  s_area[N_];
    __shared__ float4 s_sb[N_];
    __shared__ int    s_sl[N_];

    float4 w0;
    int lab0 = 0;
    if (tid < N_) {
        const float* bx = boxes + ((size_t)b * N_ + tid) * 4;
        w0 = make_float4(bx[0], bx[1], bx[2], bx[3]);
        lab0 = labels[(size_t)b * N_ + tid];
        s_area[tid] = (w0.z - w0.x) * (w0.w - w0.y);
    }
    __syncthreads();
    if (tid < N_) {
        float a = s_area[tid];
        int rank = 0;
#pragma unroll
        for (int j = 0; j < N_; j++) {
            float aj = s_area[j];
            rank += (aj > a) || (aj == a && j < tid);
        }
        s_sb[rank] = w0;
        s_sl[rank] = lab0;
    }
    __syncthreads();

    if (blockIdx.x == 0 && tid < N_) {
        g_sboxes[b][tid]  = s_sb[tid];
        g_slabels[b][tid] = s_sl[tid];
    }

    const int lane = tid & 31;
    const int rid  = blockIdx.x * 8 + (tid >> 5);
    if (rid >= NROWS) return;

    int lev, y;
    if      (rid < 128) { lev = 0; y = rid; }
    else if (rid < 192) { lev = 1; y = rid - 128; }
    else if (rid < 224) { lev = 2; y = rid - 192; }
    else if (rid < 240) { lev = 3; y = rid - 224; }
    else                { lev = 4; y = rid - 240; }

    const int   H     = c_H[lev];
    const float ps    = c_ps[lev];
    const float invps = c_invps[lev];
    const float t0m   = c_th0[lev] * 0.999f;
    const float t1m   = c_th1[lev] * 1.001f;
    const float my    = ((float)y + 0.5f) * ps;

    unsigned long long cv0 = 0ull, cv1 = 0ull, cand = 0ull;
#pragma unroll
    for (int t = 0; t < 2; t++) {
        const int n = lane + t * 32;
        float4 w = s_sb[n];
        if (my >= w.y && my <= w.w) {
            float md = fmaxf(w.z - w.x, w.w - w.y);
            if (md > t0m && 0.5f * md <= t1m) cand |= 1ull << n;

            int xlo = (int)ceilf(w.x * invps - 0.5f);
            if (((float)(xlo - 1) + 0.5f) * ps >= w.x) xlo--;
            else if (((float)xlo + 0.5f) * ps < w.x)  xlo++;
            int xhi = (int)floorf(w.z * invps - 0.5f);
            if (((float)(xhi + 1) + 0.5f) * ps <= w.z) xhi++;
            else if (((float)xhi + 0.5f) * ps > w.z)   xhi--;
            if (xlo < 0) xlo = 0;
            if (xhi > H - 1) xhi = H - 1;
            if (xlo <= xhi) {
                int l0 = xlo < 64 ? xlo : 64;
                int h0 = (xhi + 1) < 64 ? (xhi + 1) : 64;
                if (h0 > l0)
                    cv0 |= ((h0 == 64) ? ~0ull : ((1ull << h0) - 1)) & ~((1ull << l0) - 1);
                int l1 = xlo - 64 > 0 ? xlo - 64 : 0;
                int h1 = xhi + 1 - 64 > 0 ? xhi + 1 - 64 : 0;
                if (h1 > l1)
                    cv1 |= ((h1 == 64) ? ~0ull : ((1ull << h1) - 1)) & ~((1ull << l1) - 1);
            }
        }
    }
#pragma unroll
    for (int off = 16; off > 0; off >>= 1) {
        cv0  |= __shfl_xor_sync(0xFFFFFFFFu, cv0,  off);
        cv1  |= __shfl_xor_sync(0xFFFFFFFFu, cv1,  off);
        cand |= __shfl_xor_sync(0xFFFFFFFFu, cand, off);
    }
    if (lane == 0) {
        g_cov[b][lev][y][0] = cv0;
        g_cov[b][lev][y][1] = cv1;
        g_cand[b][lev][y]   = cand;
    }
}

// ---------------- K2: zeros-first fused writer, 8 channel slices ----------------
// unit = (lev, slice s in 0..7, 4-pixel group). Channel slice = [11s, min(11s+11,86)).
__global__ __launch_bounds__(256)
void fused_kernel(float* __restrict__ out) {
    const int b   = blockIdx.y;
    const int lev = c_blklev[blockIdx.x];
    const int u   = blockIdx.x * 256 + threadIdx.x;
    const int local = u - c_ubase[lev];
    const int gsh   = c_gshift4[lev];
    if (local >= (8 << gsh)) return;
    const int s = local >> gsh;
    const int g = local & ((1 << gsh) - 1);

    const int H  = c_H[lev];
    const int HH = H * H;

    const int gx4 = g << 2;
    const int y   = gx4 >> c_logH[lev];
    const int x0  = gx4 & (H - 1);

    // metadata loads kick off first (stores below don't depend on them)
    unsigned long long cand = g_cand[b][lev][y];
    const unsigned long long cov = (s == 0) ? g_cov[b][lev][y][x0 >> 6] : 0ull;

    float* rowp = out + c_base[lev] + (size_t)b * C_ * HH + (size_t)y * H + x0;
    const size_t cs = (size_t)HH;
    float* clsp = rowp + 5 * cs;
    const float4 z = make_float4(0.0f, 0.0f, 0.0f, 0.0f);

    // ---- phase 1: zero fill channels [11s, min(11s+11,86)) ----
    const int chlo = 11 * s;
    float* slicep = rowp + (size_t)chlo * cs;
    if (s == 7) {
#pragma unroll 9
        for (int i = 0; i < 9; i++)
            *reinterpret_cast<float4*>(slicep + (size_t)i * cs) = z;
    } else {
#pragma unroll 11
        for (int i = 0; i < 11; i++)
            *reinterpret_cast<float4*>(slicep + (size_t)i * cs) = z;
    }

    // ---- phase 2: sparse values / patches ----
    const int sh = x0 & 63;
    if (cand == 0ull) {
        if (s == 0) {
#pragma unroll
            for (int k = 0; k < 4; k++)
                if (!((cov >> (sh + k)) & 1ull)) clsp[k] = 1.0f;   // background
        }
        return;
    }

    const float ps  = c_ps[lev];
    const float th0 = c_th0[lev];
    const float th1 = c_th1[lev];
    const float my = ((float)y + 0.5f) * ps;
    float mx[4];
#pragma unroll
    for (int k = 0; k < 4; k++) mx[k] = ((float)(x0 + k) + 0.5f) * ps;

    int win[4] = {-1, -1, -1, -1};
    while (cand) {
        const int n = __ffsll(cand) - 1;
        cand &= cand - 1;
        float4 w = g_sboxes[b][n];
        float t   = my - w.y;
        float bo  = w.w - my;
        float tbx = fmaxf(t, bo);
#pragma unroll
        for (int k = 0; k < 4; k++) {
            float l = mx[k] - w.x, r = w.z - mx[k];
            float mxv = fmaxf(fmaxf(l, r), tbx);
            if (fminf(l, r) >= 0.0f && mxv > th0 && mxv <= th1) win[k] = n;
        }
    }

    if (s == 0) {
        bool anyw = (win[0] >= 0) || (win[1] >= 0) || (win[2] >= 0) || (win[3] >= 0);
        if (anyw) {
            float rl[4], rt[4], rr_[4], rb[4], ce[4];
#pragma unroll
            for (int k = 0; k < 4; k++) {
                if (win[k] >= 0) {
                    float4 w = g_sboxes[b][win[k]];
                    float l  = mx[k] - w.x;
                    float t  = my    - w.y;
                    float r  = w.z - mx[k];
                    float bo = w.w - my;
                    rl[k] = l; rt[k] = t; rr_[k] = r; rb[k] = bo;
                    float dx = fminf(l, r),  Dx = fmaxf(l, r);
                    float dy = fminf(t, bo), Dy = fmaxf(t, bo);
                    float arg = (dx / (Dx != 0.0f ? Dx : 1.0f)) *
                                (dy / (Dy != 0.0f ? Dy : 1.0f));
                    ce[k] = (arg > 0.0f) ? sqrtf(arg) : 0.0f;
                } else {
                    rl[k] = rt[k] = rr_[k] = rb[k] = 0.0f;
                    ce[k] = 0.0f;
                }
            }
            *reinterpret_cast<float4*>(rowp + 0 * cs) = make_float4(rl[0], rl[1], rl[2], rl[3]);
            *reinterpret_cast<float4*>(rowp + 1 * cs) = make_float4(rt[0], rt[1], rt[2], rt[3]);
            *reinterpret_cast<float4*>(rowp + 2 * cs) = make_float4(rr_[0], rr_[1], rr_[2], rr_[3]);
            *reinterpret_cast<float4*>(rowp + 3 * cs) = make_float4(rb[0], rb[1], rb[2], rb[3]);
            *reinterpret_cast<float4*>(rowp + 4 * cs) = make_float4(ce[0], ce[1], ce[2], ce[3]);
        }
#pragma unroll
        for (int k = 0; k < 4; k++) {
            if (win[k] >= 0) {
                int lab = g_slabels[b][win[k]];
                if (lab < 6) clsp[(size_t)lab * cs + k] = 1.0f;   // cls 0..5 in slice 0
            } else if (!((cov >> (sh + k)) & 1ull)) {
                clsp[k] = 1.0f;
            }
        }
    } else {
        // slice s covers cls channels [11s-5, min(11s+6, 81))
        const int lo = 11 * s - 5;
        const int hi = (s == 7) ? NUM_CLASSES : lo + 11;
#pragma unroll
        for (int k = 0; k < 4; k++) {
            if (win[k] >= 0) {
                int lab = g_slabels[b][win[k]];
                if (lab >= lo && lab < hi) clsp[(size_t)lab * cs + k] = 1.0f;
            }
        }
    }
}

extern "C" void kernel_launch(void* const* d_in, const int* in_sizes, int n_in,
                              void* d_out, int out_size) {
    const float* boxes  = (const float*)d_in[0];
    const int*   labels = (const int*)d_in[1];
    float* out = (float*)d_out;

    dim3 pgrid(31, B_);
    prep_kernel<<<pgrid, 256>>>(boxes, labels);

    dim3 grid(171, B_);    // 1368 blocks, ~9.2/SM
    fused_kernel<<<grid, 256>>>(out);
}

// round 10
// speedup vs baseline: 1.5145x; 1.1008x over previous
#include <cuda_runtime.h>
#include <cstdint>

#define B_   8
#define N_   64
#define NUM_CLASSES 81
#define C_   86
#define NLEV 5
#define NROWS 248
#define UNITS8_PER_B 43648                    // 8 slices x (HH/4) summed over levels
#define TOTAL_UNITS (B_ * UNITS8_PER_B)       // 349184
#define WBLK 128
#define WGRID 1480                            // 10 blocks/SM exactly

__constant__ int   c_H[NLEV]      = {128, 64, 32, 16, 8};
__constant__ int   c_logH[NLEV]   = {7, 6, 5, 4, 3};
__constant__ int   c_gshift4[NLEV]= {12, 10, 8, 6, 4};
__constant__ float c_ps[NLEV]     = {0.0078125f, 0.015625f, 0.03125f, 0.0625f, 0.125f};
__constant__ float c_invps[NLEV]  = {128.0f, 64.0f, 32.0f, 16.0f, 8.0f};
__constant__ float c_th0[NLEV]    = {0.0078125f, 0.0625f, 0.125f, 0.25f, 0.5f};
__constant__ float c_th1[NLEV]    = {0.0625f, 0.125f, 0.25f, 0.5f, 1.0f};
__constant__ size_t c_base[NLEV]  = {0ull, 11272192ull, 14090240ull, 14794752ull, 14970880ull};
__constant__ int   c_ubase[NLEV]  = {0, 32768, 40960, 43008, 43520};

// scratch (no allocation allowed)
__device__ float4             g_sboxes[B_][N_];
__device__ int                g_slabels[B_][N_];
__device__ unsigned long long g_cov[B_][NLEV][128][2];
__device__ unsigned long long g_cand[B_][NLEV][128];

// ---------------- K1: fused sort + per-row masks (validated R8/R9) ----------------
__global__ __launch_bounds__(256)
void prep_kernel(const float* __restrict__ boxes,
                 const int* __restrict__ labels) {
    const int b   = blockIdx.y;
    const int tid = threadIdx.x;
    __shared__ float  s_area[N_];
    __shared__ float4 s_sb[N_];
    __shared__ int    s_sl[N_];

    float4 w0;
    int lab0 = 0;
    if (tid < N_) {
        const float* bx = boxes + ((size_t)b * N_ + tid) * 4;
        w0 = make_float4(bx[0], bx[1], bx[2], bx[3]);
        lab0 = labels[(size_t)b * N_ + tid];
        s_area[tid] = (w0.z - w0.x) * (w0.w - w0.y);
    }
    __syncthreads();
    if (tid < N_) {
        float a = s_area[tid];
        int rank = 0;
#pragma unroll
        for (int j = 0; j < N_; j++) {
            float aj = s_area[j];
            rank += (aj > a) || (aj == a && j < tid);
        }
        s_sb[rank] = w0;
        s_sl[rank] = lab0;
    }
    __syncthreads();

    if (blockIdx.x == 0 && tid < N_) {
        g_sboxes[b][tid]  = s_sb[tid];
        g_slabels[b][tid] = s_sl[tid];
    }

    const int lane = tid & 31;
    const int rid  = blockIdx.x * 8 + (tid >> 5);
    if (rid >= NROWS) return;

    int lev, y;
    if      (rid < 128) { lev = 0; y = rid; }
    else if (rid < 192) { lev = 1; y = rid - 128; }
    else if (rid < 224) { lev = 2; y = rid - 192; }
    else if (rid < 240) { lev = 3; y = rid - 224; }
    else                { lev = 4; y = rid - 240; }

    const int   H     = c_H[lev];
    const float ps    = c_ps[lev];
    const float invps = c_invps[lev];
    const float t0m   = c_th0[lev] * 0.999f;
    const float t1m   = c_th1[lev] * 1.001f;
    const float my    = ((float)y + 0.5f) * ps;

    unsigned long long cv0 = 0ull, cv1 = 0ull, cand = 0ull;
#pragma unroll
    for (int t = 0; t < 2; t++) {
        const int n = lane + t * 32;
        float4 w = s_sb[n];
        if (my >= w.y && my <= w.w) {
            float md = fmaxf(w.z - w.x, w.w - w.y);
            if (md > t0m && 0.5f * md <= t1m) cand |= 1ull << n;

            int xlo = (int)ceilf(w.x * invps - 0.5f);
            if (((float)(xlo - 1) + 0.5f) * ps >= w.x) xlo--;
            else if (((float)xlo + 0.5f) * ps < w.x)  xlo++;
            int xhi = (int)floorf(w.z * invps - 0.5f);
            if (((float)(xhi + 1) + 0.5f) * ps <= w.z) xhi++;
            else if (((float)xhi + 0.5f) * ps > w.z)   xhi--;
            if (xlo < 0) xlo = 0;
            if (xhi > H - 1) xhi = H - 1;
            if (xlo <= xhi) {
                int l0 = xlo < 64 ? xlo : 64;
                int h0 = (xhi + 1) < 64 ? (xhi + 1) : 64;
                if (h0 > l0)
                    cv0 |= ((h0 == 64) ? ~0ull : ((1ull << h0) - 1)) & ~((1ull << l0) - 1);
                int l1 = xlo - 64 > 0 ? xlo - 64 : 0;
                int h1 = xhi + 1 - 64 > 0 ? xhi + 1 - 64 : 0;
                if (h1 > l1)
                    cv1 |= ((h1 == 64) ? ~0ull : ((1ull << h1) - 1)) & ~((1ull << l1) - 1);
            }
        }
    }
#pragma unroll
    for (int off = 16; off > 0; off >>= 1) {
        cv0  |= __shfl_xor_sync(0xFFFFFFFFu, cv0,  off);
        cv1  |= __shfl_xor_sync(0xFFFFFFFFu, cv1,  off);
        cand |= __shfl_xor_sync(0xFFFFFFFFu, cand, off);
    }
    if (lane == 0) {
        g_cov[b][lev][y][0] = cv0;
        g_cov[b][lev][y][1] = cv1;
        g_cand[b][lev][y]   = cand;
    }
}

// ---------------- unit worker ----------------
__device__ __forceinline__ void do_unit(float* __restrict__ out, int u) {
    const int b   = u / UNITS8_PER_B;                 // constant-divisor div
    const int r   = u - b * UNITS8_PER_B;
    const int lev = r < 32768 ? 0 : r < 40960 ? 1 : r < 43008 ? 2 : r < 43520 ? 3 : 4;
    const int local = r - c_ubase[lev];
    const int gsh   = c_gshift4[lev];
    const int s = local >> gsh;                        // slice 0..7
    const int g = local & ((1 << gsh) - 1);

    const int H  = c_H[lev];
    const int HH = H * H;
    const int gx4 = g << 2;
    const int y   = gx4 >> c_logH[lev];
    const int x0  = gx4 & (H - 1);

    // metadata loads first (independent of the zero stores)
    unsigned long long cand = g_cand[b][lev][y];
    const unsigned long long cov = (s == 0) ? g_cov[b][lev][y][x0 >> 6] : 0ull;

    float* rowp = out + c_base[lev] + (size_t)b * C_ * HH + (size_t)y * H + x0;
    const size_t cs = (size_t)HH;
    float* clsp = rowp + 5 * cs;
    const float4 z = make_float4(0.0f, 0.0f, 0.0f, 0.0f);

    // ---- phase 1: zero channels [11s, min(11s+11,86)) ----
    float* slicep = rowp + (size_t)(11 * s) * cs;
    if (s == 7) {
#pragma unroll 9
        for (int i = 0; i < 9; i++)
            *reinterpret_cast<float4*>(slicep + (size_t)i * cs) = z;
    } else {
#pragma unroll 11
        for (int i = 0; i < 11; i++)
            *reinterpret_cast<float4*>(slicep + (size_t)i * cs) = z;
    }

    // ---- phase 2: sparse values / patches ----
    const int sh = x0 & 63;
    if (cand == 0ull) {
        if (s == 0) {
#pragma unroll
            for (int k = 0; k < 4; k++)
                if (!((cov >> (sh + k)) & 1ull)) clsp[k] = 1.0f;   // background
        }
        return;
    }

    const float ps  = c_ps[lev];
    const float th0 = c_th0[lev];
    const float th1 = c_th1[lev];
    const float my = ((float)y + 0.5f) * ps;
    float mx[4];
#pragma unroll
    for (int k = 0; k < 4; k++) mx[k] = ((float)(x0 + k) + 0.5f) * ps;

    int win[4] = {-1, -1, -1, -1};
    while (cand) {
        const int n = __ffsll(cand) - 1;
        cand &= cand - 1;
        float4 w = g_sboxes[b][n];
        float t   = my - w.y;
        float bo  = w.w - my;
        float tbx = fmaxf(t, bo);
#pragma unroll
        for (int k = 0; k < 4; k++) {
            float l = mx[k] - w.x, rr = w.z - mx[k];
            float mxv = fmaxf(fmaxf(l, rr), tbx);
            if (fminf(l, rr) >= 0.0f && mxv > th0 && mxv <= th1) win[k] = n;
        }
    }

    if (s == 0) {
        bool anyw = (win[0] >= 0) || (win[1] >= 0) || (win[2] >= 0) || (win[3] >= 0);
        if (anyw) {
            float rl[4], rt[4], rr_[4], rb[4], ce[4];
#pragma unroll
            for (int k = 0; k < 4; k++) {
                if (win[k] >= 0) {
                    float4 w = g_sboxes[b][win[k]];
                    float l  = mx[k] - w.x;
                    float t  = my    - w.y;
                    float rr = w.z - mx[k];
                    float bo = w.w - my;
                    rl[k] = l; rt[k] = t; rr_[k] = rr; rb[k] = bo;
                    float dx = fminf(l, rr),  Dx = fmaxf(l, rr);
                    float dy = fminf(t, bo),  Dy = fmaxf(t, bo);
                    float arg = (dx / (Dx != 0.0f ? Dx : 1.0f)) *
                                (dy / (Dy != 0.0f ? Dy : 1.0f));
                    ce[k] = (arg > 0.0f) ? sqrtf(arg) : 0.0f;
                } else {
                    rl[k] = rt[k] = rr_[k] = rb[k] = 0.0f;
                    ce[k] = 0.0f;
                }
            }
            *reinterpret_cast<float4*>(rowp + 0 * cs) = make_float4(rl[0], rl[1], rl[2], rl[3]);
            *reinterpret_cast<float4*>(rowp + 1 * cs) = make_float4(rt[0], rt[1], rt[2], rt[3]);
            *reinterpret_cast<float4*>(rowp + 2 * cs) = make_float4(rr_[0], rr_[1], rr_[2], rr_[3]);
            *reinterpret_cast<float4*>(rowp + 3 * cs) = make_float4(rb[0], rb[1], rb[2], rb[3]);
            *reinterpret_cast<float4*>(rowp + 4 * cs) = make_float4(ce[0], ce[1], ce[2], ce[3]);
        }
#pragma unroll
        for (int k = 0; k < 4; k++) {
            if (win[k] >= 0) {
                int lab = g_slabels[b][win[k]];
                if (lab < 6) clsp[(size_t)lab * cs + k] = 1.0f;    // cls 0..5 in slice 0
            } else if (!((cov >> (sh + k)) & 1ull)) {
                clsp[k] = 1.0f;
            }
        }
    } else {
        const int lo = 11 * s - 5;                                  // cls range of slice
        const int hi = (s == 7) ? NUM_CLASSES : lo + 11;
#pragma unroll
        for (int k = 0; k < 4; k++) {
            if (win[k] >= 0) {
                int lab = g_slabels[b][win[k]];
                if (lab >= lo && lab < hi) clsp[(size_t)lab * cs + k] = 1.0f;
            }
        }
    }
}

// ---------------- K2: grid-stride writer, single resident wave ----------------
__global__ __launch_bounds__(WBLK)
void fused_kernel(float* __restrict__ out) {
    int u = blockIdx.x * WBLK + threadIdx.x;
    // TOTAL_UNITS = 349184, stride = 1480*128 = 189440 -> at most 2 iterations
    do_unit(out, u);
    u += WGRID * WBLK;
    if (u < TOTAL_UNITS) do_unit(out, u);
}

extern "C" void kernel_launch(void* const* d_in, const int* in_sizes, int n_in,
                              void* d_out, int out_size) {
    const float* boxes  = (const float*)d_in[0];
    const int*   labels = (const int*)d_in[1];
    float* out = (float*)d_out;

    dim3 pgrid(31, B_);
    prep_kernel<<<pgrid, 256>>>(boxes, labels);

    fused_kernel<<<WGRID, WBLK>>>(out);
}